// round 4
// baseline (speedup 1.0000x reference)
#include <cuda_runtime.h>
#include <cstdint>

// ---------------- problem constants ----------------
#define TOK   16384
#define DIMD  1024
#define FF    4096
#define NEXP  8
#define TM    128
#define TN    256
#define KT    32
#define ROW_TILES 264
#define R_CAP (ROW_TILES*TM)     // 33792

// smem (floats): 4 stages of A(4096) + B(8448)
#define A_STAGE 4096
#define B_STAGE 8448
#define NSTAGE  4
#define SMEM_FLOATS (NSTAGE*(A_STAGE+B_STAGE))
#define SMEM_BYTES  (SMEM_FLOATS*4 + 512)   // + sTok

// ---------------- device scratch ----------------
__device__ float g_h[(size_t)R_CAP * FF];   // hidden (tf32-rounded by gemm1 epilogue)
__device__ float g_y[(size_t)R_CAP * DIMD]; // gemm2 raw output

__device__ int   g_row_token[R_CAP];
__device__ int   g_tok_e[TOK * 2];
__device__ float g_tok_g[TOK * 2];
__device__ int   g_tok_row[TOK * 2];
__device__ int   g_counts[NEXP];
__device__ int   g_off[NEXP + 1];
__device__ int   g_cursor[NEXP];

// ---------------- helpers ----------------
__device__ __forceinline__ uint32_t smem_u32(const void* p) {
    uint32_t a;
    asm("{ .reg .u64 t; cvta.to.shared.u64 t, %1; cvt.u32.u64 %0, t; }" : "=r"(a) : "l"(p));
    return a;
}
__device__ __forceinline__ void cp_async16(uint32_t dst, const void* src) {
    asm volatile("cp.async.cg.shared.global [%0], [%1], 16;" :: "r"(dst), "l"(src));
}
#define CP_COMMIT() asm volatile("cp.async.commit_group;" ::: "memory")
#define CP_WAIT2()  asm volatile("cp.async.wait_group 2;" ::: "memory")
#define CP_WAIT0()  asm volatile("cp.async.wait_group 0;" ::: "memory")

__device__ __forceinline__ float to_tf32(float x) {
    uint32_t r;
    asm("cvt.rna.tf32.f32 %0, %1;" : "=r"(r) : "f"(x));
    return __uint_as_float(r);
}
// load f32 from smem + round to tf32 (returns bit pattern for mma)
__device__ __forceinline__ uint32_t ld_rna(const float* p) {
    uint32_t r;
    asm("cvt.rna.tf32.f32 %0, %1;" : "=r"(r) : "f"(*p));
    return r;
}
__device__ __forceinline__ uint32_t ld_raw(const float* p) {
    return __float_as_uint(*p);
}
__device__ __forceinline__ void mma_tf32(float* d,
    uint32_t a0, uint32_t a1, uint32_t a2, uint32_t a3,
    uint32_t b0, uint32_t b1) {
    asm volatile("mma.sync.aligned.m16n8k8.row.col.f32.tf32.tf32.f32 "
        "{%0,%1,%2,%3}, {%4,%5,%6,%7}, {%8,%9}, {%0,%1,%2,%3};"
        : "+f"(d[0]), "+f"(d[1]), "+f"(d[2]), "+f"(d[3])
        : "r"(a0), "r"(a1), "r"(a2), "r"(a3), "r"(b0), "r"(b1));
}

// ---------------- routing kernels ----------------
__global__ void init_kernel() {
    int i = blockIdx.x * 256 + threadIdx.x;
    if (i < NEXP) g_counts[i] = 0;
    if (i < R_CAP) g_row_token[i] = 0;
}

__global__ __launch_bounds__(256) void router_kernel(const float* __restrict__ x,
                                                     const float* __restrict__ Wg) {
    __shared__ float sWg[NEXP * DIMD];
    int tid = threadIdx.x;
    for (int i = tid; i < NEXP * DIMD; i += 256) {
        int d = i & (DIMD - 1);
        int e = i >> 10;
        sWg[i] = Wg[d * NEXP + e];
    }
    __syncthreads();
    int warp = tid >> 5, lane = tid & 31;
    int token = blockIdx.x * 8 + warp;
    const float* xr = x + (size_t)token * DIMD;
    float acc[NEXP];
#pragma unroll
    for (int e = 0; e < NEXP; e++) acc[e] = 0.f;
    for (int d = lane; d < DIMD; d += 32) {
        float xv = xr[d];
#pragma unroll
        for (int e = 0; e < NEXP; e++) acc[e] = fmaf(xv, sWg[e * DIMD + d], acc[e]);
    }
#pragma unroll
    for (int e = 0; e < NEXP; e++)
#pragma unroll
        for (int o = 16; o; o >>= 1) acc[e] += __shfl_xor_sync(0xFFFFFFFFu, acc[e], o);
    if (lane == 0) {
        int e0 = 0; float l0 = acc[0];
#pragma unroll
        for (int e = 1; e < NEXP; e++) if (acc[e] > l0) { l0 = acc[e]; e0 = e; }
        int e1 = -1; float l1 = -3.4e38f;
#pragma unroll
        for (int e = 0; e < NEXP; e++) if (e != e0 && acc[e] > l1) { l1 = acc[e]; e1 = e; }
        float g0 = 1.f / (1.f + expf(l1 - l0));
        g_tok_e[token * 2 + 0] = e0;
        g_tok_e[token * 2 + 1] = e1;
        g_tok_g[token * 2 + 0] = g0;
        g_tok_g[token * 2 + 1] = 1.f - g0;
        atomicAdd(&g_counts[e0], 1);
        atomicAdd(&g_counts[e1], 1);
    }
}

__global__ void scan_kernel() {
    if (threadIdx.x == 0) {
        int off = 0;
        for (int e = 0; e < NEXP; e++) {
            g_off[e] = off;
            g_cursor[e] = off;
            off += ((g_counts[e] + TM - 1) / TM) * TM;
        }
        g_off[NEXP] = off;
    }
}

__global__ void assign_kernel() {
    int t = blockIdx.x * 256 + threadIdx.x;
    if (t >= TOK) return;
#pragma unroll
    for (int k = 0; k < 2; k++) {
        int e = g_tok_e[t * 2 + k];
        int p = atomicAdd(&g_cursor[e], 1);
        g_row_token[p] = t;
        g_tok_row[t * 2 + k] = p;
    }
}

// ---------------- tf32 mma mainloop ----------------
struct Frag { float acc[4][8][4]; };

// GATHER: A rows indirected through sTok (gemm1 reads x directly)
template<bool GATHER>
__device__ __forceinline__ void load_tile(float* As, float* Bs, const int* sTok,
                                          int s, int kt,
                                          const float* Agm, int lda,
                                          const float* Bgm, int ldb, int tid) {
#pragma unroll
    for (int i = 0; i < 4; i++) {           // A: 128 rows x 32 floats = 1024 chunks
        int c = tid + i * 256;
        int r = c >> 3, ch = c & 7;
        uint32_t dst = smem_u32(&As[s * A_STAGE + r * 32 + ((ch ^ (r & 7)) << 2)]);
        size_t row = GATHER ? (size_t)sTok[r] : (size_t)r;
        cp_async16(dst, Agm + row * lda + kt * KT + ch * 4);
    }
#pragma unroll
    for (int i = 0; i < 8; i++) {           // B: 32 k-rows x 256 floats = 2048 chunks
        int c = tid + i * 256;
        int kr = c >> 6, ch = c & 63;
        uint32_t dst = smem_u32(&Bs[s * B_STAGE + kr * 264 + ch * 4]);
        cp_async16(dst, Bgm + (size_t)(kt * KT + kr) * ldb + ch * 4);
    }
}

// CVT_A/CVT_B: operand needs rna-tf32 rounding at fragment-load time
template<bool GATHER, bool CVT_A, bool CVT_B>
__device__ __forceinline__ void gemm_mainloop(Frag& F, float* As, float* Bs, const int* sTok,
                                              const float* Agm, int lda,
                                              const float* Bgm, int ldb,
                                              int ktiles, int tid) {
    int lane = tid & 31, wid = tid >> 5;
    int warp_m = wid & 1, warp_n = wid >> 1;
    int gid = lane >> 2, tig = lane & 3;

    int arow[4], bcol[8];
#pragma unroll
    for (int mt = 0; mt < 4; mt++) arow[mt] = (warp_m * 64 + mt * 16 + gid) * 32 + tig;
#pragma unroll
    for (int nt = 0; nt < 8; nt++) bcol[nt] = warp_n * 64 + nt * 8 + gid;

#pragma unroll
    for (int mt = 0; mt < 4; mt++)
#pragma unroll
        for (int nt = 0; nt < 8; nt++)
#pragma unroll
            for (int q = 0; q < 4; q++) F.acc[mt][nt][q] = 0.f;

    load_tile<GATHER>(As, Bs, sTok, 0, 0, Agm, lda, Bgm, ldb, tid); CP_COMMIT();
    load_tile<GATHER>(As, Bs, sTok, 1, 1, Agm, lda, Bgm, ldb, tid); CP_COMMIT();
    load_tile<GATHER>(As, Bs, sTok, 2, 2, Agm, lda, Bgm, ldb, tid); CP_COMMIT();

    for (int kt = 0; kt < ktiles; kt++) {
        int s = kt & (NSTAGE - 1);
        CP_WAIT2();
        __syncthreads();
        int ktn = kt + 3;
        if (ktn < ktiles)
            load_tile<GATHER>(As, Bs, sTok, ktn & (NSTAGE - 1), ktn, Agm, lda, Bgm, ldb, tid);
        CP_COMMIT();

        const float* as = As + s * A_STAGE;
        const float* bs = Bs + s * B_STAGE;
#pragma unroll
        for (int ks = 0; ks < 4; ks++) {
            int ax = ((2 * ks) ^ gid) << 2;
            uint32_t af[4][4];
#pragma unroll
            for (int mt = 0; mt < 4; mt++) {
                const float* p0 = as + arow[mt] + ax;
                const float* p1 = as + arow[mt] + (ax ^ 4);
                af[mt][0] = CVT_A ? ld_rna(p0)       : ld_raw(p0);
                af[mt][1] = CVT_A ? ld_rna(p0 + 256) : ld_raw(p0 + 256);
                af[mt][2] = CVT_A ? ld_rna(p1)       : ld_raw(p1);
                af[mt][3] = CVT_A ? ld_rna(p1 + 256) : ld_raw(p1 + 256);
            }
            int kb0 = (8 * ks + tig) * 264;
            uint32_t bf[8][2];
#pragma unroll
            for (int nt = 0; nt < 8; nt++) {
                const float* q0 = bs + kb0 + bcol[nt];
                const float* q1 = bs + kb0 + 4 * 264 + bcol[nt];
                bf[nt][0] = CVT_B ? ld_rna(q0) : ld_raw(q0);
                bf[nt][1] = CVT_B ? ld_rna(q1) : ld_raw(q1);
            }
#pragma unroll
            for (int mt = 0; mt < 4; mt++)
#pragma unroll
                for (int nt = 0; nt < 8; nt++)
                    mma_tf32(F.acc[mt][nt], af[mt][0], af[mt][1], af[mt][2], af[mt][3],
                             bf[nt][0], bf[nt][1]);
        }
    }
    CP_WAIT0();
}

// ---------------- GEMM1: h = tf32(relu(gather(x) @ W1[e] + b1[e])) ----------------
// grid: x = N tile (16), y = row tile (264)
__global__ __launch_bounds__(256, 1) void gemm1_kernel(const float* __restrict__ x,
                                                       const float* __restrict__ W1,
                                                       const float* __restrict__ b1) {
    extern __shared__ float sm[];
    float* As = sm;
    float* Bs = sm + NSTAGE * A_STAGE;
    int* sTok = (int*)(sm + SMEM_FLOATS);
    int tid = threadIdx.x;
    int n0 = blockIdx.x * TN;
    int row0 = blockIdx.y * TM;
    int e = 0;
#pragma unroll
    for (int i = 1; i < NEXP; i++) e += (row0 >= g_off[i]) ? 1 : 0;

    if (tid < TM) sTok[tid] = g_row_token[row0 + tid];
    __syncthreads();

    const float* Bgm = W1 + (size_t)e * DIMD * FF + n0;

    Frag F;
    gemm_mainloop<true, true, true>(F, As, Bs, sTok, x, DIMD, Bgm, FF, DIMD / KT, tid);

    int lane = tid & 31, wid = tid >> 5;
    int warp_m = wid & 1, warp_n = wid >> 1;
    int gid = lane >> 2, tig = lane & 3;
    const float* bias = b1 + e * FF + n0;

#pragma unroll
    for (int nt = 0; nt < 8; nt++) {
        int gc = warp_n * 64 + nt * 8 + tig * 2;
        float bv0 = __ldg(bias + gc), bv1 = __ldg(bias + gc + 1);
#pragma unroll
        for (int mt = 0; mt < 4; mt++) {
            int gr0 = row0 + warp_m * 64 + mt * 16 + gid;
            float2 v0, v1;
            v0.x = to_tf32(fmaxf(F.acc[mt][nt][0] + bv0, 0.f));
            v0.y = to_tf32(fmaxf(F.acc[mt][nt][1] + bv1, 0.f));
            v1.x = to_tf32(fmaxf(F.acc[mt][nt][2] + bv0, 0.f));
            v1.y = to_tf32(fmaxf(F.acc[mt][nt][3] + bv1, 0.f));
            *(float2*)(g_h + (size_t)gr0 * FF + n0 + gc) = v0;
            *(float2*)(g_h + (size_t)(gr0 + 8) * FF + n0 + gc) = v1;
        }
    }
}

// ---------------- GEMM2: y = h @ W2[e]  (bias+gate applied in combine) ----------------
__global__ __launch_bounds__(256, 1) void gemm2_kernel(const float* __restrict__ W2) {
    extern __shared__ float sm[];
    float* As = sm;
    float* Bs = sm + NSTAGE * A_STAGE;
    int tid = threadIdx.x;
    int n0 = blockIdx.x * TN;
    int row0 = blockIdx.y * TM;
    int e = 0;
#pragma unroll
    for (int i = 1; i < NEXP; i++) e += (row0 >= g_off[i]) ? 1 : 0;

    const float* Agm = g_h + (size_t)row0 * FF;
    const float* Bgm = W2 + (size_t)e * FF * DIMD + n0;

    Frag F;
    gemm_mainloop<false, false, true>(F, As, Bs, nullptr, Agm, FF, Bgm, DIMD, FF / KT, tid);

    int lane = tid & 31, wid = tid >> 5;
    int warp_m = wid & 1, warp_n = wid >> 1;
    int gid = lane >> 2, tig = lane & 3;

#pragma unroll
    for (int nt = 0; nt < 8; nt++) {
        int gc = warp_n * 64 + nt * 8 + tig * 2;
#pragma unroll
        for (int mt = 0; mt < 4; mt++) {
            int gr0 = row0 + warp_m * 64 + mt * 16 + gid;
            float2 v0 = { F.acc[mt][nt][0], F.acc[mt][nt][1] };
            float2 v1 = { F.acc[mt][nt][2], F.acc[mt][nt][3] };
            *(float2*)(g_y + (size_t)gr0 * DIMD + n0 + gc) = v0;
            *(float2*)(g_y + (size_t)(gr0 + 8) * DIMD + n0 + gc) = v1;
        }
    }
}

// ---------------- combine: out[t] = sum_k g_k*(y[row_k] + b2[e_k]) ----------------
__global__ __launch_bounds__(256) void combine_kernel(const float* __restrict__ b2,
                                                      float* __restrict__ out) {
    int t = blockIdx.x;
    int d = threadIdx.x * 4;
    int r0 = g_tok_row[t * 2], r1 = g_tok_row[t * 2 + 1];
    int e0 = g_tok_e[t * 2],   e1 = g_tok_e[t * 2 + 1];
    float gg0 = g_tok_g[t * 2], gg1 = g_tok_g[t * 2 + 1];
    float4 y0 = *(const float4*)(g_y + (size_t)r0 * DIMD + d);
    float4 y1 = *(const float4*)(g_y + (size_t)r1 * DIMD + d);
    float4 bA = *(const float4*)(b2 + (size_t)e0 * DIMD + d);
    float4 bB = *(const float4*)(b2 + (size_t)e1 * DIMD + d);
    float4 o;
    o.x = gg0 * (y0.x + bA.x) + gg1 * (y1.x + bB.x);
    o.y = gg0 * (y0.y + bA.y) + gg1 * (y1.y + bB.y);
    o.z = gg0 * (y0.z + bA.z) + gg1 * (y1.z + bB.z);
    o.w = gg0 * (y0.w + bA.w) + gg1 * (y1.w + bB.w);
    *(float4*)(out + (size_t)t * DIMD + d) = o;
}

// ---------------- host launch ----------------
extern "C" void kernel_launch(void* const* d_in, const int* in_sizes, int n_in,
                              void* d_out, int out_size) {
    const float* x  = (const float*)d_in[0];
    const float* Wg = (const float*)d_in[1];
    const float* W1 = (const float*)d_in[2];
    const float* b1 = (const float*)d_in[3];
    const float* W2 = (const float*)d_in[4];
    const float* b2 = (const float*)d_in[5];
    float* out = (float*)d_out;

    cudaFuncSetAttribute(gemm1_kernel, cudaFuncAttributeMaxDynamicSharedMemorySize, SMEM_BYTES);
    cudaFuncSetAttribute(gemm2_kernel, cudaFuncAttributeMaxDynamicSharedMemorySize, SMEM_BYTES);

    init_kernel<<<R_CAP / 256, 256>>>();
    router_kernel<<<TOK / 8, 256>>>(x, Wg);
    scan_kernel<<<1, 32>>>();
    assign_kernel<<<TOK / 256, 256>>>();
    gemm1_kernel<<<dim3(FF / TN, ROW_TILES), 256, SMEM_BYTES>>>(x, W1, b1);
    gemm2_kernel<<<dim3(DIMD / TN, ROW_TILES), 256, SMEM_BYTES>>>(W2);
    combine_kernel<<<TOK, 256>>>(b2, out);
}

// round 6
// speedup vs baseline: 1.0117x; 1.0117x over previous
#include <cuda_runtime.h>
#include <cstdint>

// ---------------- problem constants ----------------
#define TOK   16384
#define DIMD  1024
#define FF    4096
#define NEXP  8
#define TM    128
#define TN    256
#define KT    32
#define ROW_TILES 264
#define R_CAP (ROW_TILES*TM)     // 33792

// smem (floats): 4 stages of A(4096) + B(8448)
#define A_STAGE 4096
#define B_STAGE 8448
#define NSTAGE  4
#define SMEM_FLOATS (NSTAGE*(A_STAGE+B_STAGE))
#define SMEM_BYTES  (SMEM_FLOATS*4 + 512)   // + sTok

// ---------------- device scratch ----------------
__device__ float g_h[(size_t)R_CAP * FF];   // hidden (tf32-rounded by gemm1 epilogue)
__device__ float g_y[(size_t)R_CAP * DIMD]; // gemm2 raw output

__device__ int   g_row_token[R_CAP];
__device__ int   g_tok_e[TOK * 2];
__device__ float g_tok_g[TOK * 2];
__device__ int   g_tok_row[TOK * 2];
__device__ int   g_counts[NEXP];
__device__ int   g_off[NEXP + 1];
__device__ int   g_cursor[NEXP];

// ---------------- helpers ----------------
__device__ __forceinline__ uint32_t smem_u32(const void* p) {
    uint32_t a;
    asm("{ .reg .u64 t; cvta.to.shared.u64 t, %1; cvt.u32.u64 %0, t; }" : "=r"(a) : "l"(p));
    return a;
}
__device__ __forceinline__ void cp_async16(uint32_t dst, const void* src) {
    asm volatile("cp.async.cg.shared.global [%0], [%1], 16;" :: "r"(dst), "l"(src));
}
#define CP_COMMIT() asm volatile("cp.async.commit_group;" ::: "memory")
#define CP_WAIT2()  asm volatile("cp.async.wait_group 2;" ::: "memory")
#define CP_WAIT0()  asm volatile("cp.async.wait_group 0;" ::: "memory")

__device__ __forceinline__ float to_tf32(float x) {
    uint32_t r;
    asm("cvt.rna.tf32.f32 %0, %1;" : "=r"(r) : "f"(x));
    return __uint_as_float(r);
}
__device__ __forceinline__ uint32_t ld_rna(const float* p) {
    uint32_t r;
    asm("cvt.rna.tf32.f32 %0, %1;" : "=r"(r) : "f"(*p));
    return r;
}
__device__ __forceinline__ uint32_t ld_raw(const float* p) {
    return __float_as_uint(*p);
}
__device__ __forceinline__ void mma_tf32(float* d,
    uint32_t a0, uint32_t a1, uint32_t a2, uint32_t a3,
    uint32_t b0, uint32_t b1) {
    asm volatile("mma.sync.aligned.m16n8k8.row.col.f32.tf32.tf32.f32 "
        "{%0,%1,%2,%3}, {%4,%5,%6,%7}, {%8,%9}, {%0,%1,%2,%3};"
        : "+f"(d[0]), "+f"(d[1]), "+f"(d[2]), "+f"(d[3])
        : "r"(a0), "r"(a1), "r"(a2), "r"(a3), "r"(b0), "r"(b1));
}

// ---------------- routing kernels ----------------
__global__ void init_kernel() {
    int i = blockIdx.x * 256 + threadIdx.x;
    if (i < NEXP) g_counts[i] = 0;
    if (i < R_CAP) g_row_token[i] = 0;
}

__global__ __launch_bounds__(256) void router_kernel(const float* __restrict__ x,
                                                     const float* __restrict__ Wg) {
    __shared__ float sWg[NEXP * DIMD];
    int tid = threadIdx.x;
    for (int i = tid; i < NEXP * DIMD; i += 256) {
        int d = i & (DIMD - 1);
        int e = i >> 10;
        sWg[i] = Wg[d * NEXP + e];
    }
    __syncthreads();
    int warp = tid >> 5, lane = tid & 31;
    int token = blockIdx.x * 8 + warp;
    const float* xr = x + (size_t)token * DIMD;
    float acc[NEXP];
#pragma unroll
    for (int e = 0; e < NEXP; e++) acc[e] = 0.f;
    for (int d = lane; d < DIMD; d += 32) {
        float xv = xr[d];
#pragma unroll
        for (int e = 0; e < NEXP; e++) acc[e] = fmaf(xv, sWg[e * DIMD + d], acc[e]);
    }
#pragma unroll
    for (int e = 0; e < NEXP; e++)
#pragma unroll
        for (int o = 16; o; o >>= 1) acc[e] += __shfl_xor_sync(0xFFFFFFFFu, acc[e], o);
    if (lane == 0) {
        int e0 = 0; float l0 = acc[0];
#pragma unroll
        for (int e = 1; e < NEXP; e++) if (acc[e] > l0) { l0 = acc[e]; e0 = e; }
        int e1 = -1; float l1 = -3.4e38f;
#pragma unroll
        for (int e = 0; e < NEXP; e++) if (e != e0 && acc[e] > l1) { l1 = acc[e]; e1 = e; }
        float g0 = 1.f / (1.f + expf(l1 - l0));
        g_tok_e[token * 2 + 0] = e0;
        g_tok_e[token * 2 + 1] = e1;
        g_tok_g[token * 2 + 0] = g0;
        g_tok_g[token * 2 + 1] = 1.f - g0;
        atomicAdd(&g_counts[e0], 1);
        atomicAdd(&g_counts[e1], 1);
    }
}

__global__ void scan_kernel() {
    if (threadIdx.x == 0) {
        int off = 0;
        for (int e = 0; e < NEXP; e++) {
            g_off[e] = off;
            g_cursor[e] = off;
            off += ((g_counts[e] + TM - 1) / TM) * TM;
        }
        g_off[NEXP] = off;
    }
}

__global__ void assign_kernel() {
    int t = blockIdx.x * 256 + threadIdx.x;
    if (t >= TOK) return;
#pragma unroll
    for (int k = 0; k < 2; k++) {
        int e = g_tok_e[t * 2 + k];
        int p = atomicAdd(&g_cursor[e], 1);
        g_row_token[p] = t;
        g_tok_row[t * 2 + k] = p;
    }
}

// ---------------- tf32 mma mainloop ----------------
struct Frag { float acc[4][8][4]; };

// GATHER: A rows indirected through sTok (gemm1 reads x directly)
template<bool GATHER>
__device__ __forceinline__ void load_tile(float* As, float* Bs, const int* sTok,
                                          int s, int kt,
                                          const float* Agm, int lda,
                                          const float* Bgm, int ldb, int tid) {
#pragma unroll
    for (int i = 0; i < 4; i++) {           // A: 128 rows x 32 floats = 1024 chunks
        int c = tid + i * 256;
        int r = c >> 3, ch = c & 7;
        uint32_t dst = smem_u32(&As[s * A_STAGE + r * 32 + ((ch ^ (r & 7)) << 2)]);
        size_t row = GATHER ? (size_t)sTok[r] : (size_t)r;
        cp_async16(dst, Agm + row * lda + kt * KT + ch * 4);
    }
#pragma unroll
    for (int i = 0; i < 8; i++) {           // B: 32 k-rows x 256 floats = 2048 chunks
        int c = tid + i * 256;
        int kr = c >> 6, ch = c & 63;
        uint32_t dst = smem_u32(&Bs[s * B_STAGE + kr * 264 + ch * 4]);
        cp_async16(dst, Bgm + (size_t)(kt * KT + kr) * ldb + ch * 4);
    }
}

// CVT_A/CVT_B: operand needs rna-tf32 rounding at fragment-load time
template<bool GATHER, bool CVT_A, bool CVT_B>
__device__ __forceinline__ void gemm_mainloop(Frag& F, float* As, float* Bs, const int* sTok,
                                              const float* Agm, int lda,
                                              const float* Bgm, int ldb,
                                              int ktiles, int tid) {
    int lane = tid & 31, wid = tid >> 5;
    int warp_m = wid & 1, warp_n = wid >> 1;
    int gid = lane >> 2, tig = lane & 3;

    int arow[4], bcol[8];
#pragma unroll
    for (int mt = 0; mt < 4; mt++) arow[mt] = (warp_m * 64 + mt * 16 + gid) * 32 + tig;
#pragma unroll
    for (int nt = 0; nt < 8; nt++) bcol[nt] = warp_n * 64 + nt * 8 + gid;

#pragma unroll
    for (int mt = 0; mt < 4; mt++)
#pragma unroll
        for (int nt = 0; nt < 8; nt++)
#pragma unroll
            for (int q = 0; q < 4; q++) F.acc[mt][nt][q] = 0.f;

    load_tile<GATHER>(As, Bs, sTok, 0, 0, Agm, lda, Bgm, ldb, tid); CP_COMMIT();
    load_tile<GATHER>(As, Bs, sTok, 1, 1, Agm, lda, Bgm, ldb, tid); CP_COMMIT();
    load_tile<GATHER>(As, Bs, sTok, 2, 2, Agm, lda, Bgm, ldb, tid); CP_COMMIT();

    for (int kt = 0; kt < ktiles; kt++) {
        int s = kt & (NSTAGE - 1);
        CP_WAIT2();
        __syncthreads();
        int ktn = kt + 3;
        if (ktn < ktiles)
            load_tile<GATHER>(As, Bs, sTok, ktn & (NSTAGE - 1), ktn, Agm, lda, Bgm, ldb, tid);
        CP_COMMIT();

        const float* as = As + s * A_STAGE;
        const float* bs = Bs + s * B_STAGE;
#pragma unroll
        for (int ks = 0; ks < 4; ks++) {
            int ax = ((2 * ks) ^ gid) << 2;
            uint32_t af[4][4];
#pragma unroll
            for (int mt = 0; mt < 4; mt++) {
                const float* p0 = as + arow[mt] + ax;
                const float* p1 = as + arow[mt] + (ax ^ 4);
                af[mt][0] = CVT_A ? ld_rna(p0)       : ld_raw(p0);
                af[mt][1] = CVT_A ? ld_rna(p0 + 256) : ld_raw(p0 + 256);
                af[mt][2] = CVT_A ? ld_rna(p1)       : ld_raw(p1);
                af[mt][3] = CVT_A ? ld_rna(p1 + 256) : ld_raw(p1 + 256);
            }
            int kb0 = (8 * ks + tig) * 264;
            uint32_t bf[8][2];
#pragma unroll
            for (int nt = 0; nt < 8; nt++) {
                const float* q0 = bs + kb0 + bcol[nt];
                const float* q1 = bs + kb0 + 4 * 264 + bcol[nt];
                bf[nt][0] = CVT_B ? ld_rna(q0) : ld_raw(q0);
                bf[nt][1] = CVT_B ? ld_rna(q1) : ld_raw(q1);
            }
#pragma unroll
            for (int mt = 0; mt < 4; mt++)
#pragma unroll
                for (int nt = 0; nt < 8; nt++)
                    mma_tf32(F.acc[mt][nt], af[mt][0], af[mt][1], af[mt][2], af[mt][3],
                             bf[nt][0], bf[nt][1]);
        }
    }
    CP_WAIT0();
}

// ---------------- GEMM1: h = tf32(relu(gather(x) @ W1[e] + b1[e])) ----------------
// grid: x = row tile (264, fastest -> concurrent CTAs share the SAME B strip in L2),
//       y = N tile (16)
__global__ __launch_bounds__(256, 1) void gemm1_kernel(const float* __restrict__ x,
                                                       const float* __restrict__ W1,
                                                       const float* __restrict__ b1) {
    extern __shared__ float sm[];
    float* As = sm;
    float* Bs = sm + NSTAGE * A_STAGE;
    int* sTok = (int*)(sm + SMEM_FLOATS);
    int tid = threadIdx.x;
    int row0 = blockIdx.x * TM;
    int n0 = blockIdx.y * TN;
    int e = 0;
#pragma unroll
    for (int i = 1; i < NEXP; i++) e += (row0 >= g_off[i]) ? 1 : 0;

    if (tid < TM) sTok[tid] = g_row_token[row0 + tid];
    __syncthreads();

    const float* Bgm = W1 + (size_t)e * DIMD * FF + n0;

    Frag F;
    gemm_mainloop<true, true, true>(F, As, Bs, sTok, x, DIMD, Bgm, FF, DIMD / KT, tid);

    int lane = tid & 31, wid = tid >> 5;
    int warp_m = wid & 1, warp_n = wid >> 1;
    int gid = lane >> 2, tig = lane & 3;
    const float* bias = b1 + e * FF + n0;

#pragma unroll
    for (int nt = 0; nt < 8; nt++) {
        int gc = warp_n * 64 + nt * 8 + tig * 2;
        float bv0 = __ldg(bias + gc), bv1 = __ldg(bias + gc + 1);
#pragma unroll
        for (int mt = 0; mt < 4; mt++) {
            int gr0 = row0 + warp_m * 64 + mt * 16 + gid;
            float2 v0, v1;
            v0.x = to_tf32(fmaxf(F.acc[mt][nt][0] + bv0, 0.f));
            v0.y = to_tf32(fmaxf(F.acc[mt][nt][1] + bv1, 0.f));
            v1.x = to_tf32(fmaxf(F.acc[mt][nt][2] + bv0, 0.f));
            v1.y = to_tf32(fmaxf(F.acc[mt][nt][3] + bv1, 0.f));
            *(float2*)(g_h + (size_t)gr0 * FF + n0 + gc) = v0;
            *(float2*)(g_h + (size_t)(gr0 + 8) * FF + n0 + gc) = v1;
        }
    }
}

// ---------------- GEMM2: y = h @ W2[e]  (bias+gate applied in combine) ----------------
// grid: x = row tile (264), y = N tile (4)  -- body mapping matches this launch
__global__ __launch_bounds__(256, 1) void gemm2_kernel(const float* __restrict__ W2) {
    extern __shared__ float sm[];
    float* As = sm;
    float* Bs = sm + NSTAGE * A_STAGE;
    int tid = threadIdx.x;
    int row0 = blockIdx.x * TM;
    int n0 = blockIdx.y * TN;
    int e = 0;
#pragma unroll
    for (int i = 1; i < NEXP; i++) e += (row0 >= g_off[i]) ? 1 : 0;

    const float* Agm = g_h + (size_t)row0 * FF;
    const float* Bgm = W2 + (size_t)e * FF * DIMD + n0;

    Frag F;
    gemm_mainloop<false, false, true>(F, As, Bs, nullptr, Agm, FF, Bgm, DIMD, FF / KT, tid);

    int lane = tid & 31, wid = tid >> 5;
    int warp_m = wid & 1, warp_n = wid >> 1;
    int gid = lane >> 2, tig = lane & 3;

#pragma unroll
    for (int nt = 0; nt < 8; nt++) {
        int gc = warp_n * 64 + nt * 8 + tig * 2;
#pragma unroll
        for (int mt = 0; mt < 4; mt++) {
            int gr0 = row0 + warp_m * 64 + mt * 16 + gid;
            float2 v0 = { F.acc[mt][nt][0], F.acc[mt][nt][1] };
            float2 v1 = { F.acc[mt][nt][2], F.acc[mt][nt][3] };
            *(float2*)(g_y + (size_t)gr0 * DIMD + n0 + gc) = v0;
            *(float2*)(g_y + (size_t)(gr0 + 8) * DIMD + n0 + gc) = v1;
        }
    }
}

// ---------------- combine: out[t] = sum_k g_k*(y[row_k] + b2[e_k]) ----------------
__global__ __launch_bounds__(256) void combine_kernel(const float* __restrict__ b2,
                                                      float* __restrict__ out) {
    int t = blockIdx.x;
    int d = threadIdx.x * 4;
    int r0 = g_tok_row[t * 2], r1 = g_tok_row[t * 2 + 1];
    int e0 = g_tok_e[t * 2],   e1 = g_tok_e[t * 2 + 1];
    float gg0 = g_tok_g[t * 2], gg1 = g_tok_g[t * 2 + 1];
    float4 y0 = *(const float4*)(g_y + (size_t)r0 * DIMD + d);
    float4 y1 = *(const float4*)(g_y + (size_t)r1 * DIMD + d);
    float4 bA = *(const float4*)(b2 + (size_t)e0 * DIMD + d);
    float4 bB = *(const float4*)(b2 + (size_t)e1 * DIMD + d);
    float4 o;
    o.x = gg0 * (y0.x + bA.x) + gg1 * (y1.x + bB.x);
    o.y = gg0 * (y0.y + bA.y) + gg1 * (y1.y + bB.y);
    o.z = gg0 * (y0.z + bA.z) + gg1 * (y1.z + bB.z);
    o.w = gg0 * (y0.w + bA.w) + gg1 * (y1.w + bB.w);
    *(float4*)(out + (size_t)t * DIMD + d) = o;
}

// ---------------- host launch ----------------
extern "C" void kernel_launch(void* const* d_in, const int* in_sizes, int n_in,
                              void* d_out, int out_size) {
    const float* x  = (const float*)d_in[0];
    const float* Wg = (const float*)d_in[1];
    const float* W1 = (const float*)d_in[2];
    const float* b1 = (const float*)d_in[3];
    const float* W2 = (const float*)d_in[4];
    const float* b2 = (const float*)d_in[5];
    float* out = (float*)d_out;

    cudaFuncSetAttribute(gemm1_kernel, cudaFuncAttributeMaxDynamicSharedMemorySize, SMEM_BYTES);
    cudaFuncSetAttribute(gemm2_kernel, cudaFuncAttributeMaxDynamicSharedMemorySize, SMEM_BYTES);

    init_kernel<<<R_CAP / 256, 256>>>();
    router_kernel<<<TOK / 8, 256>>>(x, Wg);
    scan_kernel<<<1, 32>>>();
    assign_kernel<<<TOK / 256, 256>>>();
    gemm1_kernel<<<dim3(ROW_TILES, FF / TN), 256, SMEM_BYTES>>>(x, W1, b1);
    gemm2_kernel<<<dim3(ROW_TILES, DIMD / TN), 256, SMEM_BYTES>>>(W2);
    combine_kernel<<<TOK, 256>>>(b2, out);
}

// round 7
// speedup vs baseline: 1.0581x; 1.0458x over previous
#include <cuda_runtime.h>
#include <cstdint>

// ---------------- problem constants ----------------
#define TOK   16384
#define DIMD  1024
#define FF    4096
#define NEXP  8
#define TM    128
#define TN    128
#define KT    32
#define ROW_TILES 264
#define R_CAP (ROW_TILES*TM)     // 33792

// smem (floats): 3 stages of A(4096) + B(4352); 2 CTAs/SM
#define A_STAGE 4096
#define B_STAGE 4352             // 32 k-rows x 136 (128 + 8 pad)
#define NSTAGE  3
#define SMEM_FLOATS (NSTAGE*(A_STAGE+B_STAGE))
#define SMEM_BYTES  (SMEM_FLOATS*4)

// ---------------- device scratch ----------------
__device__ float g_xg[(size_t)R_CAP * DIMD];            // gathered x, tf32-rounded
__device__ float g_h[(size_t)R_CAP * FF];               // hidden, tf32-rounded
__device__ float g_y[(size_t)R_CAP * DIMD];             // gemm2 raw output
__device__ float g_w1r[(size_t)NEXP * DIMD * FF];       // tf32-rounded W1 [e][d][f]
__device__ float g_w2r[(size_t)NEXP * FF * DIMD];       // tf32-rounded W2 [e][f][d]

__device__ int   g_row_token[R_CAP];
__device__ int   g_tok_e[TOK * 2];
__device__ float g_tok_g[TOK * 2];
__device__ int   g_tok_row[TOK * 2];
__device__ int   g_counts[NEXP];
__device__ int   g_off[NEXP + 1];
__device__ int   g_cursor[NEXP];

// ---------------- helpers ----------------
__device__ __forceinline__ uint32_t smem_u32(const void* p) {
    uint32_t a;
    asm("{ .reg .u64 t; cvta.to.shared.u64 t, %1; cvt.u32.u64 %0, t; }" : "=r"(a) : "l"(p));
    return a;
}
__device__ __forceinline__ void cp_async16(uint32_t dst, const void* src) {
    asm volatile("cp.async.cg.shared.global [%0], [%1], 16;" :: "r"(dst), "l"(src));
}
#define CP_COMMIT() asm volatile("cp.async.commit_group;" ::: "memory")
#define CP_WAIT1()  asm volatile("cp.async.wait_group 1;" ::: "memory")
#define CP_WAIT0()  asm volatile("cp.async.wait_group 0;" ::: "memory")

__device__ __forceinline__ float to_tf32(float x) {
    uint32_t r;
    asm("cvt.rna.tf32.f32 %0, %1;" : "=r"(r) : "f"(x));
    return __uint_as_float(r);
}
__device__ __forceinline__ void mma_tf32(float* d,
    uint32_t a0, uint32_t a1, uint32_t a2, uint32_t a3,
    uint32_t b0, uint32_t b1) {
    asm volatile("mma.sync.aligned.m16n8k8.row.col.f32.tf32.tf32.f32 "
        "{%0,%1,%2,%3}, {%4,%5,%6,%7}, {%8,%9}, {%0,%1,%2,%3};"
        : "+f"(d[0]), "+f"(d[1]), "+f"(d[2]), "+f"(d[3])
        : "r"(a0), "r"(a1), "r"(a2), "r"(a3), "r"(b0), "r"(b1));
}

// ---------------- routing kernels ----------------
__global__ void init_kernel() {
    int i = blockIdx.x * 256 + threadIdx.x;
    if (i < NEXP) g_counts[i] = 0;
    if (i < R_CAP) g_row_token[i] = 0;
}

__global__ __launch_bounds__(256) void router_kernel(const float* __restrict__ x,
                                                     const float* __restrict__ Wg) {
    __shared__ float sWg[NEXP * DIMD];
    int tid = threadIdx.x;
    for (int i = tid; i < NEXP * DIMD; i += 256) {
        int d = i & (DIMD - 1);
        int e = i >> 10;
        sWg[i] = Wg[d * NEXP + e];
    }
    __syncthreads();
    int warp = tid >> 5, lane = tid & 31;
    int token = blockIdx.x * 8 + warp;
    const float* xr = x + (size_t)token * DIMD;
    float acc[NEXP];
#pragma unroll
    for (int e = 0; e < NEXP; e++) acc[e] = 0.f;
    for (int d = lane; d < DIMD; d += 32) {
        float xv = xr[d];
#pragma unroll
        for (int e = 0; e < NEXP; e++) acc[e] = fmaf(xv, sWg[e * DIMD + d], acc[e]);
    }
#pragma unroll
    for (int e = 0; e < NEXP; e++)
#pragma unroll
        for (int o = 16; o; o >>= 1) acc[e] += __shfl_xor_sync(0xFFFFFFFFu, acc[e], o);
    if (lane == 0) {
        int e0 = 0; float l0 = acc[0];
#pragma unroll
        for (int e = 1; e < NEXP; e++) if (acc[e] > l0) { l0 = acc[e]; e0 = e; }
        int e1 = -1; float l1 = -3.4e38f;
#pragma unroll
        for (int e = 0; e < NEXP; e++) if (e != e0 && acc[e] > l1) { l1 = acc[e]; e1 = e; }
        float g0 = 1.f / (1.f + expf(l1 - l0));
        g_tok_e[token * 2 + 0] = e0;
        g_tok_e[token * 2 + 1] = e1;
        g_tok_g[token * 2 + 0] = g0;
        g_tok_g[token * 2 + 1] = 1.f - g0;
        atomicAdd(&g_counts[e0], 1);
        atomicAdd(&g_counts[e1], 1);
    }
}

__global__ void scan_kernel() {
    if (threadIdx.x == 0) {
        int off = 0;
        for (int e = 0; e < NEXP; e++) {
            g_off[e] = off;
            g_cursor[e] = off;
            off += ((g_counts[e] + TM - 1) / TM) * TM;
        }
        g_off[NEXP] = off;
    }
}

__global__ void assign_kernel() {
    int t = blockIdx.x * 256 + threadIdx.x;
    if (t >= TOK) return;
#pragma unroll
    for (int k = 0; k < 2; k++) {
        int e = g_tok_e[t * 2 + k];
        int p = atomicAdd(&g_cursor[e], 1);
        g_row_token[p] = t;
        g_tok_row[t * 2 + k] = p;
    }
}

// gather x rows (padded segments), round to tf32
__global__ __launch_bounds__(256) void gather_x_kernel(const float* __restrict__ x) {
    size_t base = ((size_t)blockIdx.x * 256 + threadIdx.x) * 4;
    int row = (int)(base >> 10);
    int col = (int)(base & 1023);
    int tok = g_row_token[row];
    float4 v = *(const float4*)(x + (size_t)tok * DIMD + col);
    v.x = to_tf32(v.x); v.y = to_tf32(v.y); v.z = to_tf32(v.z); v.w = to_tf32(v.w);
    *(float4*)(g_xg + base) = v;
}

// elementwise tf32 rounding for weights
__global__ __launch_bounds__(256) void round_w_kernel(const float* __restrict__ src,
                                                      float* __restrict__ dst) {
    size_t i = ((size_t)blockIdx.x * 256 + threadIdx.x) * 4;
    float4 v = *(const float4*)(src + i);
    v.x = to_tf32(v.x); v.y = to_tf32(v.y); v.z = to_tf32(v.z); v.w = to_tf32(v.w);
    *(float4*)(dst + i) = v;
}

// ---------------- tf32 mma mainloop (TM=128, TN=128, 8 warps 2x4, warp tile 64x32) ----------------
struct Frag { float acc[4][4][4]; };

__device__ __forceinline__ void load_tile(float* As, float* Bs, int s, int kt,
                                          const float* Agm, int lda,
                                          const float* Bgm, int ldb, int tid) {
#pragma unroll
    for (int i = 0; i < 4; i++) {           // A: 128 rows x 32 floats = 1024 chunks
        int c = tid + i * 256;
        int r = c >> 3, ch = c & 7;
        uint32_t dst = smem_u32(&As[s * A_STAGE + r * 32 + ((ch ^ (r & 7)) << 2)]);
        cp_async16(dst, Agm + (size_t)r * lda + kt * KT + ch * 4);
    }
#pragma unroll
    for (int i = 0; i < 4; i++) {           // B: 32 k-rows x 128 floats = 1024 chunks
        int c = tid + i * 256;
        int kr = c >> 5, ch = c & 31;
        uint32_t dst = smem_u32(&Bs[s * B_STAGE + kr * 136 + ch * 4]);
        cp_async16(dst, Bgm + (size_t)(kt * KT + kr) * ldb + ch * 4);
    }
}

__device__ __forceinline__ void gemm_mainloop(Frag& F, float* As, float* Bs,
                                              const float* Agm, int lda,
                                              const float* Bgm, int ldb,
                                              int ktiles, int tid) {
    int lane = tid & 31, wid = tid >> 5;
    int warp_m = wid & 1, warp_n = wid >> 1;
    int gid = lane >> 2, tig = lane & 3;

    int arow[4], bcol[4];
#pragma unroll
    for (int mt = 0; mt < 4; mt++) arow[mt] = (warp_m * 64 + mt * 16 + gid) * 32 + tig;
#pragma unroll
    for (int nt = 0; nt < 4; nt++) bcol[nt] = warp_n * 32 + nt * 8 + gid;

#pragma unroll
    for (int mt = 0; mt < 4; mt++)
#pragma unroll
        for (int nt = 0; nt < 4; nt++)
#pragma unroll
            for (int q = 0; q < 4; q++) F.acc[mt][nt][q] = 0.f;

    load_tile(As, Bs, 0, 0, Agm, lda, Bgm, ldb, tid); CP_COMMIT();
    load_tile(As, Bs, 1, 1, Agm, lda, Bgm, ldb, tid); CP_COMMIT();

    for (int kt = 0; kt < ktiles; kt++) {
        int s = kt % 3;
        CP_WAIT1();
        __syncthreads();
        int ktn = kt + 2;
        if (ktn < ktiles)
            load_tile(As, Bs, ktn % 3, ktn, Agm, lda, Bgm, ldb, tid);
        CP_COMMIT();

        const float* as = As + s * A_STAGE;
        const float* bs = Bs + s * B_STAGE;
#pragma unroll
        for (int ks = 0; ks < 4; ks++) {
            int ax = ((2 * ks) ^ gid) << 2;
            uint32_t af[4][4];
#pragma unroll
            for (int mt = 0; mt < 4; mt++) {
                af[mt][0] = __float_as_uint(as[arow[mt] + ax]);
                af[mt][1] = __float_as_uint(as[arow[mt] + ax + 256]);
                af[mt][2] = __float_as_uint(as[arow[mt] + (ax ^ 4)]);
                af[mt][3] = __float_as_uint(as[arow[mt] + (ax ^ 4) + 256]);
            }
            int kb0 = (8 * ks + tig) * 136;
            uint32_t bf[4][2];
#pragma unroll
            for (int nt = 0; nt < 4; nt++) {
                bf[nt][0] = __float_as_uint(bs[kb0 + bcol[nt]]);
                bf[nt][1] = __float_as_uint(bs[kb0 + 4 * 136 + bcol[nt]]);
            }
#pragma unroll
            for (int mt = 0; mt < 4; mt++)
#pragma unroll
                for (int nt = 0; nt < 4; nt++)
                    mma_tf32(F.acc[mt][nt], af[mt][0], af[mt][1], af[mt][2], af[mt][3],
                             bf[nt][0], bf[nt][1]);
        }
    }
    CP_WAIT0();
}

// ---------------- GEMM1: h = tf32(relu(g_xg @ W1r[e] + b1[e])) ----------------
// bid.x = row*2 + n_lo (row-fastest, N-pairs co-resident), bid.y = n_hi
__global__ __launch_bounds__(256, 2) void gemm1_kernel(const float* __restrict__ b1) {
    extern __shared__ float sm[];
    float* As = sm;
    float* Bs = sm + NSTAGE * A_STAGE;
    int tid = threadIdx.x;
    int row0 = (blockIdx.x >> 1) * TM;
    int n0 = (blockIdx.y * 2 + (blockIdx.x & 1)) * TN;
    int e = 0;
#pragma unroll
    for (int i = 1; i < NEXP; i++) e += (row0 >= g_off[i]) ? 1 : 0;

    const float* Agm = g_xg + (size_t)row0 * DIMD;
    const float* Bgm = g_w1r + (size_t)e * DIMD * FF + n0;

    Frag F;
    gemm_mainloop(F, As, Bs, Agm, DIMD, Bgm, FF, DIMD / KT, tid);

    int lane = tid & 31, wid = tid >> 5;
    int warp_m = wid & 1, warp_n = wid >> 1;
    int gid = lane >> 2, tig = lane & 3;
    const float* bias = b1 + e * FF + n0;

#pragma unroll
    for (int nt = 0; nt < 4; nt++) {
        int gc = warp_n * 32 + nt * 8 + tig * 2;
        float bv0 = __ldg(bias + gc), bv1 = __ldg(bias + gc + 1);
#pragma unroll
        for (int mt = 0; mt < 4; mt++) {
            int gr0 = row0 + warp_m * 64 + mt * 16 + gid;
            float2 v0, v1;
            v0.x = to_tf32(fmaxf(F.acc[mt][nt][0] + bv0, 0.f));
            v0.y = to_tf32(fmaxf(F.acc[mt][nt][1] + bv1, 0.f));
            v1.x = to_tf32(fmaxf(F.acc[mt][nt][2] + bv0, 0.f));
            v1.y = to_tf32(fmaxf(F.acc[mt][nt][3] + bv1, 0.f));
            *(float2*)(g_h + (size_t)gr0 * FF + n0 + gc) = v0;
            *(float2*)(g_h + (size_t)(gr0 + 8) * FF + n0 + gc) = v1;
        }
    }
}

// ---------------- GEMM2: y = h @ W2r[e]  (bias+gate applied in combine) ----------------
__global__ __launch_bounds__(256, 2) void gemm2_kernel() {
    extern __shared__ float sm[];
    float* As = sm;
    float* Bs = sm + NSTAGE * A_STAGE;
    int tid = threadIdx.x;
    int row0 = (blockIdx.x >> 1) * TM;
    int n0 = (blockIdx.y * 2 + (blockIdx.x & 1)) * TN;
    int e = 0;
#pragma unroll
    for (int i = 1; i < NEXP; i++) e += (row0 >= g_off[i]) ? 1 : 0;

    const float* Agm = g_h + (size_t)row0 * FF;
    const float* Bgm = g_w2r + (size_t)e * FF * DIMD + n0;

    Frag F;
    gemm_mainloop(F, As, Bs, Agm, FF, Bgm, DIMD, FF / KT, tid);

    int lane = tid & 31, wid = tid >> 5;
    int warp_m = wid & 1, warp_n = wid >> 1;
    int gid = lane >> 2, tig = lane & 3;

#pragma unroll
    for (int nt = 0; nt < 4; nt++) {
        int gc = warp_n * 32 + nt * 8 + tig * 2;
#pragma unroll
        for (int mt = 0; mt < 4; mt++) {
            int gr0 = row0 + warp_m * 64 + mt * 16 + gid;
            float2 v0 = { F.acc[mt][nt][0], F.acc[mt][nt][1] };
            float2 v1 = { F.acc[mt][nt][2], F.acc[mt][nt][3] };
            *(float2*)(g_y + (size_t)gr0 * DIMD + n0 + gc) = v0;
            *(float2*)(g_y + (size_t)(gr0 + 8) * DIMD + n0 + gc) = v1;
        }
    }
}

// ---------------- combine: out[t] = sum_k g_k*(y[row_k] + b2[e_k]) ----------------
__global__ __launch_bounds__(256) void combine_kernel(const float* __restrict__ b2,
                                                      float* __restrict__ out) {
    int t = blockIdx.x;
    int d = threadIdx.x * 4;
    int r0 = g_tok_row[t * 2], r1 = g_tok_row[t * 2 + 1];
    int e0 = g_tok_e[t * 2],   e1 = g_tok_e[t * 2 + 1];
    float gg0 = g_tok_g[t * 2], gg1 = g_tok_g[t * 2 + 1];
    float4 y0 = *(const float4*)(g_y + (size_t)r0 * DIMD + d);
    float4 y1 = *(const float4*)(g_y + (size_t)r1 * DIMD + d);
    float4 bA = *(const float4*)(b2 + (size_t)e0 * DIMD + d);
    float4 bB = *(const float4*)(b2 + (size_t)e1 * DIMD + d);
    float4 o;
    o.x = gg0 * (y0.x + bA.x) + gg1 * (y1.x + bB.x);
    o.y = gg0 * (y0.y + bA.y) + gg1 * (y1.y + bB.y);
    o.z = gg0 * (y0.z + bA.z) + gg1 * (y1.z + bB.z);
    o.w = gg0 * (y0.w + bA.w) + gg1 * (y1.w + bB.w);
    *(float4*)(out + (size_t)t * DIMD + d) = o;
}

// ---------------- host launch ----------------
extern "C" void kernel_launch(void* const* d_in, const int* in_sizes, int n_in,
                              void* d_out, int out_size) {
    const float* x  = (const float*)d_in[0];
    const float* Wg = (const float*)d_in[1];
    const float* W1 = (const float*)d_in[2];
    const float* b1 = (const float*)d_in[3];
    const float* W2 = (const float*)d_in[4];
    const float* b2 = (const float*)d_in[5];
    float* out = (float*)d_out;

    cudaFuncSetAttribute(gemm1_kernel, cudaFuncAttributeMaxDynamicSharedMemorySize, SMEM_BYTES);
    cudaFuncSetAttribute(gemm2_kernel, cudaFuncAttributeMaxDynamicSharedMemorySize, SMEM_BYTES);

    float *pW1r, *pW2r;
    cudaGetSymbolAddress((void**)&pW1r, g_w1r);
    cudaGetSymbolAddress((void**)&pW2r, g_w2r);

    init_kernel<<<R_CAP / 256, 256>>>();
    router_kernel<<<TOK / 8, 256>>>(x, Wg);
    scan_kernel<<<1, 32>>>();
    assign_kernel<<<TOK / 256, 256>>>();
    gather_x_kernel<<<(R_CAP * (DIMD / 4)) / 256, 256>>>(x);
    round_w_kernel<<<(NEXP * DIMD * FF / 4) / 256, 256>>>(W1, pW1r);
    round_w_kernel<<<(NEXP * FF * DIMD / 4) / 256, 256>>>(W2, pW2r);
    gemm1_kernel<<<dim3(ROW_TILES * 2, FF / (TN * 2)), 256, SMEM_BYTES>>>(b1);
    gemm2_kernel<<<dim3(ROW_TILES * 2, DIMD / (TN * 2)), 256, SMEM_BYTES>>>();
    combine_kernel<<<TOK, 256>>>(b2, out);
}